// round 13
// baseline (speedup 1.0000x reference)
#include <cuda_runtime.h>

// Problem dims
#define B_  2048
#define M_  128
#define D_  512
#define H_  512
#define KU_ 1024

// GEMM tiling: 128x32 tile, BK=16, 256 threads, 8Mx2N micro-tile, M-packed f32x2
#define BM 128
#define BN 32
#define BK 16
#define AS_LD (BM + 4)   // 132
#define WS_LD (BN + 4)   // 36

#define NCOMPUTE 256     // 16 tiles x 16 n-slots
#define NGRID    296     // + 40 pure mean workers (exact 2-per-SM residency)
#define JOBS_PT  128     // mean jobs per tile (2 rows per job, 2 modalities)

typedef unsigned long long u64;
typedef unsigned int u32;

// Scratch + flags (device globals — no allocation allowed)
__device__ float g_mi[B_ * H_];
__device__ float g_mt[B_ * H_];
__device__ float g_u [B_ * H_];
__device__ u32   g_tjob[16];
__device__ u32   g_mcnt[16];
__device__ u32   g_ucnt[16];

// ---------------------------------------------------------------------------
__device__ __forceinline__ u32 ld_acq(const u32* p) {
    u32 v; asm volatile("ld.acquire.gpu.global.u32 %0, [%1];" : "=r"(v) : "l"(p)); return v;
}
__device__ __forceinline__ void red_rel(u32* p) {
    asm volatile("red.release.gpu.global.add.u32 [%0], 1;" :: "l"(p) : "memory");
}
__device__ __forceinline__ void fma2(u64& d, u64 a, u64 b) {
    asm volatile("fma.rn.f32x2 %0, %1, %2, %0;" : "+l"(d) : "l"(a), "l"(b));
}
__device__ __forceinline__ u64 pack2(float x) {
    u64 r; asm("mov.b64 %0, {%1, %1};" : "=l"(r) : "f"(x)); return r;
}
__device__ __forceinline__ float2 unpk(u64 v) {
    float2 r; asm("mov.b64 {%0,%1}, %2;" : "=f"(r.x), "=f"(r.y) : "l"(v)); return r;
}

// ---------------------------------------------------------------------------
__device__ __forceinline__ void sts_a(float (*As)[AS_LD], const float4& v, int row, int cv) {
    As[cv + 0][row] = v.x; As[cv + 1][row] = v.y;
    As[cv + 2][row] = v.z; As[cv + 3][row] = v.w;
}
__device__ __forceinline__ void sts_w(float (*Ws)[WS_LD], const float4& v, int row, int cv) {
    Ws[cv + 0][row] = v.x; Ws[cv + 1][row] = v.y;
    Ws[cv + 2][row] = v.z; Ws[cv + 3][row] = v.w;
}

// Inner: 8M (4 packed pairs) x 2N per thread. ty=m-group(0..15), tx=n-group(0..15)
__device__ __forceinline__ void tile_fma(
    u64 acc[4][2], const float (*As)[AS_LD], const float (*Ws)[WS_LD], int ty, int tx)
{
#pragma unroll
    for (int kk = 0; kk < BK; kk++) {
        const u64* ap = reinterpret_cast<const u64*>(&As[kk][ty * 8]);
        ulonglong2 a01 = *reinterpret_cast<const ulonglong2*>(ap);
        ulonglong2 a23 = *reinterpret_cast<const ulonglong2*>(ap + 2);
        float2 w = *reinterpret_cast<const float2*>(&Ws[kk][tx * 2]);
        u64 w0 = pack2(w.x), w1 = pack2(w.y);
        fma2(acc[0][0], a01.x, w0); fma2(acc[1][0], a01.y, w0);
        fma2(acc[2][0], a23.x, w0); fma2(acc[3][0], a23.y, w0);
        fma2(acc[0][1], a01.x, w1); fma2(acc[1][1], a01.y, w1);
        fma2(acc[2][1], a23.x, w1); fma2(acc[3][1], a23.y, w1);
    }
}

// Pipelined K=512 phase. A rows [bm,bm+128), W0(+W1) rows [bn,bn+32).
__device__ __forceinline__ void run_phase(
    u64 acc[4][2],
    const float* __restrict__ A,
    const float* __restrict__ W0, const float* __restrict__ W1,
    float As[2][BK][AS_LD], float Ws[2][BK][WS_LD],
    int bm, int bn, int tid, int ty, int tx)
{
    const int r0 = tid >> 2;
    const int cv = (tid & 3) << 2;
    const int NT = H_ / BK;   // 32

    float4 a0, a1, wv;
    {
        a0 = *reinterpret_cast<const float4*>(A + (size_t)(bm + r0) * H_ + cv);
        a1 = *reinterpret_cast<const float4*>(A + (size_t)(bm + r0 + 64) * H_ + cv);
        sts_a(As[0], a0, r0, cv); sts_a(As[0], a1, r0 + 64, cv);
        if (tid < 128) {
            wv = *reinterpret_cast<const float4*>(W0 + (size_t)(bn + (r0 & 31)) * H_ + cv);
            if (W1) {
                float4 w2 = *reinterpret_cast<const float4*>(W1 + (size_t)(bn + (r0 & 31)) * H_ + cv);
                wv.x += w2.x; wv.y += w2.y; wv.z += w2.z; wv.w += w2.w;
            }
            sts_w(Ws[0], wv, r0 & 31, cv);
        }
    }
    __syncthreads();

    int p = 0;
    for (int t = 0; t < NT; t++) {
        if (t + 1 < NT) {
            int kt = (t + 1) * BK;
            a0 = *reinterpret_cast<const float4*>(A + (size_t)(bm + r0) * H_ + kt + cv);
            a1 = *reinterpret_cast<const float4*>(A + (size_t)(bm + r0 + 64) * H_ + kt + cv);
            if (tid < 128) {
                wv = *reinterpret_cast<const float4*>(W0 + (size_t)(bn + (r0 & 31)) * H_ + kt + cv);
                if (W1) {
                    float4 w2 = *reinterpret_cast<const float4*>(W1 + (size_t)(bn + (r0 & 31)) * H_ + kt + cv);
                    wv.x += w2.x; wv.y += w2.y; wv.z += w2.z; wv.w += w2.w;
                }
            }
        }
        tile_fma(acc, As[p], Ws[p], ty, tx);
        if (t + 1 < NT) {
            sts_a(As[p ^ 1], a0, r0, cv); sts_a(As[p ^ 1], a1, r0 + 64, cv);
            if (tid < 128) sts_w(Ws[p ^ 1], wv, r0 & 31, cv);
        }
        __syncthreads();
        p ^= 1;
    }
}

// One mean job: 2 batch rows of one modality within tile t.
__device__ __forceinline__ void mean_job(
    int t, int inner, int tid,
    const float* __restrict__ btf, const float* __restrict__ bif)
{
    const int modal = inner >> 6;
    const int row   = t * 128 + (inner & 63) * 2 + (tid >> 7);
    const int col   = tid & 127;
    const float* src = modal ? btf : bif;
    float*       dst = modal ? g_mt : g_mi;

    const float4* q = reinterpret_cast<const float4*>(src)
                      + (size_t)row * (M_ * H_ / 4) + col;
    float4 sA = make_float4(0.f, 0.f, 0.f, 0.f);
    float4 sB = make_float4(0.f, 0.f, 0.f, 0.f);
#pragma unroll
    for (int mb = 0; mb < M_; mb += 8) {
        float4 v[8];
#pragma unroll
        for (int k = 0; k < 8; k++)
            v[k] = q[(size_t)(mb + k) * (H_ / 4)];
#pragma unroll
        for (int k = 0; k < 8; k += 2) {
            sA.x += v[k].x;     sA.y += v[k].y;
            sA.z += v[k].z;     sA.w += v[k].w;
            sB.x += v[k + 1].x; sB.y += v[k + 1].y;
            sB.z += v[k + 1].z; sB.w += v[k + 1].w;
        }
    }
    const float s = 1.0f / (float)M_;
    reinterpret_cast<float4*>(dst)[(size_t)row * (H_ / 4) + col] =
        make_float4((sA.x + sB.x) * s, (sA.y + sB.y) * s,
                    (sA.z + sB.z) * s, (sA.w + sB.w) * s);
}

// ---------------------------------------------------------------------------
__global__ void zero_flags() {
    if (threadIdx.x < 16) {
        g_tjob[threadIdx.x] = 0;
        g_mcnt[threadIdx.x] = 0;
        g_ucnt[threadIdx.x] = 0;
    }
}

// ---------------------------------------------------------------------------
// grid=296, 256 threads, 2 CTAs/SM (all co-resident, wave 1).
//   CTAs 0..255   : compute. tile t=cid>>4, n-slot cid&15.
//                   gemm_user -> release ucnt[t] -> steal own-tile mean jobs
//                   -> wait mcnt[t] -> phases mi,mt -> wait ucnt[t] -> phase u
//                   -> bias+ReLU epilogue.
//   CTAs 256..295 : pure mean workers, drain tile queues in order, exit.
// ---------------------------------------------------------------------------
__global__ void __launch_bounds__(256, 2) fused_all(
    const float* __restrict__ it,  const float* __restrict__ ii,
    const float* __restrict__ btf, const float* __restrict__ bif,
    const float* __restrict__ Wu,  const float* __restrict__ bu,
    const float* __restrict__ Wli, const float* __restrict__ bli,
    const float* __restrict__ Wri, const float* __restrict__ Wlt,
    const float* __restrict__ blt, const float* __restrict__ Wrt,
    float* __restrict__ out)
{
    __shared__ float As[2][BK][AS_LD];
    __shared__ float Ws[2][BK][WS_LD];
    __shared__ int s_job;

    const int cid = blockIdx.x;
    const int tid = threadIdx.x;

    if (cid >= NCOMPUTE) {
        // ================= pure mean workers =================
        for (int t = 0; t < 16; t++) {
            for (;;) {
                if (tid == 0) s_job = (int)atomicAdd(&g_tjob[t], 1u);
                __syncthreads();
                int j = s_job;
                __syncthreads();
                if (j >= JOBS_PT) break;
                mean_job(t, j, tid, btf, bif);
                __syncthreads();
                if (tid == 0) red_rel(&g_mcnt[t]);
            }
        }
        return;
    }

    // ================= compute CTAs =================
    const int tile = cid >> 4;
    const int bm   = tile * BM;
    const int bn   = (cid & 15) * BN;
    const int tx   = tid & 15;
    const int ty   = tid >> 4;
    const int r0   = tid >> 2;
    const int cv   = (tid & 3) << 2;

    // ---- Stage 1: gemm_user tile: u = concat(it,ii) @ Wu^T + bu  (128x32) ----
    {
        u64 acc[4][2];
#pragma unroll
        for (int i = 0; i < 4; i++) { acc[i][0] = 0ull; acc[i][1] = 0ull; }

        const int NT = KU_ / BK;   // 64
        float4 a0, a1, wv;
        {
            int kg = cv;
            const float* p0 = (kg < D_) ? (it + (size_t)(bm + r0) * D_ + kg)
                                        : (ii + (size_t)(bm + r0) * D_ + (kg - D_));
            const float* p1 = (kg < D_) ? (it + (size_t)(bm + r0 + 64) * D_ + kg)
                                        : (ii + (size_t)(bm + r0 + 64) * D_ + (kg - D_));
            a0 = *reinterpret_cast<const float4*>(p0);
            a1 = *reinterpret_cast<const float4*>(p1);
            sts_a(As[0], a0, r0, cv); sts_a(As[0], a1, r0 + 64, cv);
            if (tid < 128) {
                wv = *reinterpret_cast<const float4*>(Wu + (size_t)(bn + (r0 & 31)) * KU_ + cv);
                sts_w(Ws[0], wv, r0 & 31, cv);
            }
        }
        __syncthreads();

        int p = 0;
        for (int t = 0; t < NT; t++) {
            if (t + 1 < NT) {
                int kt = (t + 1) * BK;
                int kg = kt + cv;
                const float* p0 = (kg < D_) ? (it + (size_t)(bm + r0) * D_ + kg)
                                            : (ii + (size_t)(bm + r0) * D_ + (kg - D_));
                const float* p1 = (kg < D_) ? (it + (size_t)(bm + r0 + 64) * D_ + kg)
                                            : (ii + (size_t)(bm + r0 + 64) * D_ + (kg - D_));
                a0 = *reinterpret_cast<const float4*>(p0);
                a1 = *reinterpret_cast<const float4*>(p1);
                if (tid < 128)
                    wv = *reinterpret_cast<const float4*>(Wu + (size_t)(bn + (r0 & 31)) * KU_ + kt + cv);
            }
            tile_fma(acc, As[p], Ws[p], ty, tx);
            if (t + 1 < NT) {
                sts_a(As[p ^ 1], a0, r0, cv); sts_a(As[p ^ 1], a1, r0 + 64, cv);
                if (tid < 128) sts_w(Ws[p ^ 1], wv, r0 & 31, cv);
            }
            __syncthreads();
            p ^= 1;
        }

        float2 bb = *reinterpret_cast<const float2*>(bu + bn + tx * 2);
#pragma unroll
        for (int i = 0; i < 4; i++) {
            float2 c0 = unpk(acc[i][0]);   // col n0: rows r, r+1
            float2 c1 = unpk(acc[i][1]);   // col n1
            int r = bm + ty * 8 + 2 * i;
            *reinterpret_cast<float2*>(g_u + (size_t)r * H_ + bn + tx * 2) =
                make_float2(c0.x + bb.x, c1.x + bb.y);
            *reinterpret_cast<float2*>(g_u + (size_t)(r + 1) * H_ + bn + tx * 2) =
                make_float2(c0.y + bb.x, c1.y + bb.y);
        }
    }
    __syncthreads();
    if (tid == 0) red_rel(&g_ucnt[tile]);

    // ---- Stage 2: steal this tile's mean jobs ----
    for (;;) {
        if (tid == 0) s_job = (int)atomicAdd(&g_tjob[tile], 1u);
        __syncthreads();
        int j = s_job;
        __syncthreads();
        if (j >= JOBS_PT) break;
        mean_job(tile, j, tid, btf, bif);
        __syncthreads();
        if (tid == 0) red_rel(&g_mcnt[tile]);
    }

    // ---- Stage 3: output accumulation ----
    u64 acc[4][2];
#pragma unroll
    for (int i = 0; i < 4; i++) { acc[i][0] = 0ull; acc[i][1] = 0ull; }

    if (tid == 0) { while (ld_acq(&g_mcnt[tile]) < JOBS_PT) __nanosleep(128); }
    __syncthreads();

    run_phase(acc, g_mi, Wli, (const float*)0, As, Ws, bm, bn, tid, ty, tx);
    run_phase(acc, g_mt, Wlt, (const float*)0, As, Ws, bm, bn, tid, ty, tx);

    if (tid == 0) { while (ld_acq(&g_ucnt[tile]) < 16u) __nanosleep(128); }
    __syncthreads();

    run_phase(acc, g_u, Wri, Wrt, As, Ws, bm, bn, tid, ty, tx);

    // epilogue: + (bli+blt), ReLU
    float2 b1 = *reinterpret_cast<const float2*>(bli + bn + tx * 2);
    float2 b2 = *reinterpret_cast<const float2*>(blt + bn + tx * 2);
    float2 bb = make_float2(b1.x + b2.x, b1.y + b2.y);
#pragma unroll
    for (int i = 0; i < 4; i++) {
        float2 c0 = unpk(acc[i][0]);
        float2 c1 = unpk(acc[i][1]);
        int r = bm + ty * 8 + 2 * i;
        *reinterpret_cast<float2*>(out + (size_t)r * H_ + bn + tx * 2) =
            make_float2(fmaxf(c0.x + bb.x, 0.f), fmaxf(c1.x + bb.y, 0.f));
        *reinterpret_cast<float2*>(out + (size_t)(r + 1) * H_ + bn + tx * 2) =
            make_float2(fmaxf(c0.y + bb.x, 0.f), fmaxf(c1.y + bb.y, 0.f));
    }
}

// ---------------------------------------------------------------------------
extern "C" void kernel_launch(void* const* d_in, const int* in_sizes, int n_in,
                              void* d_out, int out_size) {
    (void)in_sizes; (void)n_in; (void)out_size;
    const float* it  = (const float*)d_in[0];
    const float* ii  = (const float*)d_in[1];
    const float* btf = (const float*)d_in[2];
    const float* bif = (const float*)d_in[3];
    const float* Wu  = (const float*)d_in[4];
    const float* bu  = (const float*)d_in[5];
    const float* Wli = (const float*)d_in[6];
    const float* bli = (const float*)d_in[7];
    const float* Wri = (const float*)d_in[8];
    const float* Wlt = (const float*)d_in[9];
    const float* blt = (const float*)d_in[10];
    const float* Wrt = (const float*)d_in[11];
    float* out = (float*)d_out;

    zero_flags<<<1, 32>>>();
    fused_all<<<NGRID, 256>>>(it, ii, btf, bif, Wu, bu, Wli, bli, Wri,
                              Wlt, blt, Wrt, out);
}